// round 1
// baseline (speedup 1.0000x reference)
#include <cuda_runtime.h>
#include <math_constants.h>

#define N_NODES_C 100000
#define D_MODEL_C 256
#define N_SLOTS_C 512
#define BLK_M 64
#define THREADS_C 512
#define NC1 128      // slot chunk for GEMM1
#define KC1 32       // k (d_model) chunk for GEMM1
#define KC2 16       // slot chunk for GEMM2
#define MS1_STRIDE 33

// smem (floats): Qs[64][256] | Ss[64][512] | Bf[max(128*33, 16*256)]
#define QS_FLOATS (BLK_M * D_MODEL_C)          // 16384
#define SS_FLOATS (BLK_M * N_SLOTS_C)          // 32768
#define BF_FLOATS (NC1 * MS1_STRIDE)           // 4224 >= 16*256
#define SMEM_FLOATS (QS_FLOATS + SS_FLOATS + BF_FLOATS)
#define SMEM_BYTES (SMEM_FLOATS * 4)           // 213504

__global__ __launch_bounds__(THREADS_C, 1)
void fused_mem_read_kernel(const float* __restrict__ query,
                           const float* __restrict__ mem_attr,
                           const float* __restrict__ mem_struct,
                           float* __restrict__ out) {
    extern __shared__ float smem[];
    float* Qs = smem;                       // [64][256]
    float* Ss = smem + QS_FLOATS;           // [64][512]
    float* Bf = smem + QS_FLOATS + SS_FLOATS;

    const int tid = threadIdx.x;
    const int n0 = blockIdx.x * BLK_M;
    const float* __restrict__ mem = (blockIdx.y == 0) ? mem_attr : mem_struct;
    float* __restrict__ outg = out + (size_t)blockIdx.y * (size_t)N_NODES_C * 512u;

    // ---- Load Q tile (zero-pad OOB rows) ----
    {
        const float4* q4 = (const float4*)query;
        float4* qs4 = (float4*)Qs;
        #pragma unroll
        for (int it = 0; it < (BLK_M * D_MODEL_C / 4) / THREADS_C; it++) {
            int i = tid + it * THREADS_C;           // float4 index, 0..4095
            int r = i >> 6;                          // 64 float4 per row
            int c = i & 63;
            int gr = n0 + r;
            float4 v = make_float4(0.f, 0.f, 0.f, 0.f);
            if (gr < N_NODES_C) v = q4[(size_t)gr * 64 + c];
            qs4[r * 64 + c] = v;
        }
    }
    __syncthreads();

    const int rg = tid >> 5;     // 0..15  -> rows rg*4 .. rg*4+3
    const int lane = tid & 31;   // column lane

    // =========================== GEMM1: S = Q @ M^T ===========================
    for (int nc = 0; nc < N_SLOTS_C; nc += NC1) {
        float acc[4][4];
        #pragma unroll
        for (int i = 0; i < 4; i++)
            #pragma unroll
            for (int j = 0; j < 4; j++) acc[i][j] = 0.f;

        for (int kc = 0; kc < D_MODEL_C; kc += KC1) {
            __syncthreads();
            // Stage mem[nc..nc+127][kc..kc+31] into Bf[slot][k] with stride 33.
            // 1024 float4 gmem reads -> 2 per thread; scalar conflict-free STS.
            #pragma unroll
            for (int it = 0; it < 2; it++) {
                int idx = tid + it * THREADS_C;      // 0..1023
                int slot_l = idx >> 3;               // 0..127
                int kq = idx & 7;                    // 0..7 (float4 group)
                float4 v = *(const float4*)&mem[(size_t)(nc + slot_l) * D_MODEL_C + kc + kq * 4];
                float* dst = &Bf[slot_l * MS1_STRIDE + kq * 4];
                dst[0] = v.x; dst[1] = v.y; dst[2] = v.z; dst[3] = v.w;
            }
            __syncthreads();

            #pragma unroll
            for (int kk = 0; kk < KC1; kk++) {
                float a[4], b[4];
                #pragma unroll
                for (int i = 0; i < 4; i++) a[i] = Qs[(rg * 4 + i) * D_MODEL_C + kc + kk];
                #pragma unroll
                for (int j = 0; j < 4; j++) b[j] = Bf[(lane + 32 * j) * MS1_STRIDE + kk];
                #pragma unroll
                for (int i = 0; i < 4; i++)
                    #pragma unroll
                    for (int j = 0; j < 4; j++)
                        acc[i][j] = fmaf(a[i], b[j], acc[i][j]);
            }
        }
        // Write S chunk. Warp rg writes only rows rg*4..rg*4+3 (its own rows).
        #pragma unroll
        for (int i = 0; i < 4; i++)
            #pragma unroll
            for (int j = 0; j < 4; j++)
                Ss[(rg * 4 + i) * N_SLOTS_C + nc + lane + 32 * j] = acc[i][j];
    }
    __syncthreads();

    // =========================== Row softmax (in place) ===========================
    // Warp rg owns rows rg*4..rg*4+3 (the rows it produced).
    #pragma unroll
    for (int i = 0; i < 4; i++) {
        float* srow = &Ss[(rg * 4 + i) * N_SLOTS_C];
        float v[16];
        float m = -CUDART_INF_F;
        #pragma unroll
        for (int t = 0; t < 16; t++) {
            v[t] = srow[lane + 32 * t];
            m = fmaxf(m, v[t]);
        }
        #pragma unroll
        for (int o = 16; o > 0; o >>= 1) m = fmaxf(m, __shfl_xor_sync(0xffffffffu, m, o));
        float s = 0.f;
        #pragma unroll
        for (int t = 0; t < 16; t++) {
            v[t] = __expf(v[t] - m);
            s += v[t];
        }
        #pragma unroll
        for (int o = 16; o > 0; o >>= 1) s += __shfl_xor_sync(0xffffffffu, s, o);
        float inv = 1.0f / s;
        #pragma unroll
        for (int t = 0; t < 16; t++) srow[lane + 32 * t] = v[t] * inv;
    }

    // =========================== GEMM2: R = P @ M ===========================
    float acc2[4][8];
    #pragma unroll
    for (int i = 0; i < 4; i++)
        #pragma unroll
        for (int j = 0; j < 8; j++) acc2[i][j] = 0.f;

    for (int kc = 0; kc < N_SLOTS_C; kc += KC2) {
        __syncthreads();
        // Stage mem[kc..kc+15][0..255] into Bf[kk][d] (natural layout), float4 copy.
        #pragma unroll
        for (int it = 0; it < 2; it++) {
            int idx = tid + it * THREADS_C;          // 0..1023 float4s
            int row = idx >> 6;                      // 0..15
            int cq = idx & 63;
            float4 v = *(const float4*)&mem[(size_t)(kc + row) * D_MODEL_C + cq * 4];
            *(float4*)&Bf[row * D_MODEL_C + cq * 4] = v;
        }
        __syncthreads();

        #pragma unroll
        for (int kk = 0; kk < KC2; kk++) {
            float a[4], b[8];
            #pragma unroll
            for (int i = 0; i < 4; i++) a[i] = Ss[(rg * 4 + i) * N_SLOTS_C + kc + kk];
            #pragma unroll
            for (int j = 0; j < 8; j++) b[j] = Bf[kk * D_MODEL_C + lane + 32 * j];
            #pragma unroll
            for (int i = 0; i < 4; i++)
                #pragma unroll
                for (int j = 0; j < 8; j++)
                    acc2[i][j] = fmaf(a[i], b[j], acc2[i][j]);
        }
    }

    // ---- Write R half of output ----
    #pragma unroll
    for (int i = 0; i < 4; i++) {
        int gr = n0 + rg * 4 + i;
        if (gr < N_NODES_C) {
            float* orow = outg + (size_t)gr * 512 + 256;
            #pragma unroll
            for (int j = 0; j < 8; j++) orow[lane + 32 * j] = acc2[i][j];
        }
    }

    // ---- Write Q copy half of output (Qs is stable since load) ----
    {
        const float4* qs4 = (const float4*)Qs;
        #pragma unroll
        for (int it = 0; it < (BLK_M * 64) / THREADS_C; it++) {
            int i = tid + it * THREADS_C;            // float4 index 0..4095
            int r = i >> 6;
            int c = i & 63;
            int gr = n0 + r;
            if (gr < N_NODES_C)
                ((float4*)(outg + (size_t)gr * 512))[c] = qs4[r * 64 + c];
        }
    }
}

extern "C" void kernel_launch(void* const* d_in, const int* in_sizes, int n_in,
                              void* d_out, int out_size) {
    const float* query      = (const float*)d_in[0];
    const float* mem_attr   = (const float*)d_in[1];
    const float* mem_struct = (const float*)d_in[2];
    float* out = (float*)d_out;

    cudaFuncSetAttribute(fused_mem_read_kernel,
                         cudaFuncAttributeMaxDynamicSharedMemorySize, SMEM_BYTES);

    dim3 grid((N_NODES_C + BLK_M - 1) / BLK_M, 2);
    fused_mem_read_kernel<<<grid, THREADS_C, SMEM_BYTES>>>(query, mem_attr, mem_struct, out);
}

// round 2
// speedup vs baseline: 1.2467x; 1.2467x over previous
#include <cuda_runtime.h>
#include <math_constants.h>

#define N_NODES_C 100000
#define D_MODEL_C 256
#define N_SLOTS_C 512
#define BLK_M 64
#define THREADS_C 512
#define KC1 8     // k-chunk (d_model) for GEMM1 staging
#define KC2 16    // k-chunk (slots) for GEMM2 staging

// smem floats: Qst[256][64] | Ss[64][512] | Stg[8192]
#define QST_F (D_MODEL_C * BLK_M)        // 16384
#define SS_F  (BLK_M * N_SLOTS_C)        // 32768
#define STG_F 8192                        // max(2*KC1*512, 2*KC2*256) = 8192
#define SMEM_BYTES ((QST_F + SS_F + STG_F) * 4)   // 229376

__global__ __launch_bounds__(THREADS_C, 1)
void fused_mem_read_v2(const float* __restrict__ query,
                       const float* __restrict__ mem_attr,
                       const float* __restrict__ mem_struct,
                       float* __restrict__ out) {
    extern __shared__ float smem[];
    float* Qst = smem;                    // [256][64]  (k-major Q)
    float* Ss  = smem + QST_F;            // [64][512]
    float* Stg = smem + QST_F + SS_F;     // staging, double-buffered

    const int tid = threadIdx.x;
    const int n0 = blockIdx.x * BLK_M;
    const float* __restrict__ mem = (blockIdx.y == 0) ? mem_attr : mem_struct;
    float* __restrict__ outg = out + (size_t)blockIdx.y * (size_t)N_NODES_C * 512u;

    // ---- Load Q tile TRANSPOSED into Qst[k][m]  (conflict-free: bank = r%32) ----
    {
        const float4* q4 = (const float4*)query;
        #pragma unroll
        for (int it = 0; it < 8; it++) {
            int idx = tid + it * THREADS_C;   // 0..4095
            int r = idx & 63;                 // lanes span 32 consecutive r
            int c4 = idx >> 6;                // 0..63
            int gr = n0 + r;
            float4 v = make_float4(0.f, 0.f, 0.f, 0.f);
            if (gr < N_NODES_C) v = q4[(size_t)gr * 64 + c4];
            Qst[(c4 * 4 + 0) * 64 + r] = v.x;
            Qst[(c4 * 4 + 1) * 64 + r] = v.y;
            Qst[(c4 * 4 + 2) * 64 + r] = v.z;
            Qst[(c4 * 4 + 3) * 64 + r] = v.w;
        }
    }

    const int rg = tid >> 6;      // 0..7   rows rg*8..rg*8+7
    const int cn = tid & 63;      // 0..63  slots cn*4..+3 and 256+cn*4..+3

    // ================= GEMM1: S = Q @ M^T  (64x512, 8x8 reg tiles) =================
    float acc[8][8];
    #pragma unroll
    for (int i = 0; i < 8; i++)
        #pragma unroll
        for (int j = 0; j < 8; j++) acc[i][j] = 0.f;

    // prefetch + stage chunk 0:  Stg[buf*KC1 + kk][slot], slot = tid (bank-clean)
    const float* mrow = mem + (size_t)tid * D_MODEL_C;
    float4 p0 = *(const float4*)(mrow + 0);
    float4 p1 = *(const float4*)(mrow + 4);
    {
        float* d = Stg; // buf 0
        d[(0)*512 + tid] = p0.x; d[(1)*512 + tid] = p0.y;
        d[(2)*512 + tid] = p0.z; d[(3)*512 + tid] = p0.w;
        d[(4)*512 + tid] = p1.x; d[(5)*512 + tid] = p1.y;
        d[(6)*512 + tid] = p1.z; d[(7)*512 + tid] = p1.w;
    }
    __syncthreads();

    for (int kc = 0; kc < D_MODEL_C; kc += KC1) {
        const int buf = (kc >> 3) & 1;
        const int nbuf = buf ^ 1;
        const bool more = (kc + KC1) < D_MODEL_C;
        if (more) {
            p0 = *(const float4*)(mrow + kc + KC1 + 0);
            p1 = *(const float4*)(mrow + kc + KC1 + 4);
        }
        const float* bb = Stg + buf * (KC1 * 512);
        #pragma unroll
        for (int kk = 0; kk < KC1; kk++) {
            float4 a0 = *(const float4*)&Qst[(kc + kk) * 64 + rg * 8];      // broadcast
            float4 a1 = *(const float4*)&Qst[(kc + kk) * 64 + rg * 8 + 4];  // broadcast
            float4 b0 = *(const float4*)&bb[kk * 512 + cn * 4];
            float4 b1 = *(const float4*)&bb[kk * 512 + 256 + cn * 4];
            float a[8] = {a0.x, a0.y, a0.z, a0.w, a1.x, a1.y, a1.z, a1.w};
            float b[8] = {b0.x, b0.y, b0.z, b0.w, b1.x, b1.y, b1.z, b1.w};
            #pragma unroll
            for (int i = 0; i < 8; i++)
                #pragma unroll
                for (int j = 0; j < 8; j++)
                    acc[i][j] = fmaf(a[i], b[j], acc[i][j]);
        }
        if (more) {
            float* d = Stg + nbuf * (KC1 * 512);
            d[(0)*512 + tid] = p0.x; d[(1)*512 + tid] = p0.y;
            d[(2)*512 + tid] = p0.z; d[(3)*512 + tid] = p0.w;
            d[(4)*512 + tid] = p1.x; d[(5)*512 + tid] = p1.y;
            d[(6)*512 + tid] = p1.z; d[(7)*512 + tid] = p1.w;
        }
        __syncthreads();
    }

    // ---- write S (STS.128, conflict-free) ----
    #pragma unroll
    for (int i = 0; i < 8; i++) {
        float* srow = &Ss[(rg * 8 + i) * N_SLOTS_C];
        *(float4*)&srow[cn * 4]       = make_float4(acc[i][0], acc[i][1], acc[i][2], acc[i][3]);
        *(float4*)&srow[256 + cn * 4] = make_float4(acc[i][4], acc[i][5], acc[i][6], acc[i][7]);
    }
    __syncthreads();

    // ================= Row softmax (warp w owns rows w*4..w*4+3) =================
    {
        const int w = tid >> 5, lane = tid & 31;
        #pragma unroll
        for (int i = 0; i < 4; i++) {
            float* srow = &Ss[(w * 4 + i) * N_SLOTS_C];
            float v[16];
            float m = -CUDART_INF_F;
            #pragma unroll
            for (int t = 0; t < 16; t++) { v[t] = srow[lane + 32 * t]; m = fmaxf(m, v[t]); }
            #pragma unroll
            for (int o = 16; o > 0; o >>= 1) m = fmaxf(m, __shfl_xor_sync(0xffffffffu, m, o));
            float s = 0.f;
            #pragma unroll
            for (int t = 0; t < 16; t++) { v[t] = __expf(v[t] - m); s += v[t]; }
            #pragma unroll
            for (int o = 16; o > 0; o >>= 1) s += __shfl_xor_sync(0xffffffffu, s, o);
            float inv = 1.0f / s;
            #pragma unroll
            for (int t = 0; t < 16; t++) srow[lane + 32 * t] = v[t] * inv;
        }
    }
    __syncthreads();

    // ================= GEMM2: R = P @ M  (64x256, 8x4 reg tiles) =================
    float acc2[8][4];
    #pragma unroll
    for (int i = 0; i < 8; i++)
        #pragma unroll
        for (int j = 0; j < 4; j++) acc2[i][j] = 0.f;

    // staging: Stg2[buf*KC2 + row][d], row-natural, 2 float4/thread per chunk
    const int r2 = tid >> 6;      // 0..7
    const int c4b = tid & 63;     // 0..63
    float4 q0, q1;
    q0 = *(const float4*)&mem[(size_t)(r2)     * D_MODEL_C + c4b * 4];
    q1 = *(const float4*)&mem[(size_t)(r2 + 8) * D_MODEL_C + c4b * 4];
    {
        float* d = Stg;
        *(float4*)&d[(r2)     * 256 + c4b * 4] = q0;
        *(float4*)&d[(r2 + 8) * 256 + c4b * 4] = q1;
    }
    __syncthreads();

    for (int kc = 0; kc < N_SLOTS_C; kc += KC2) {
        const int buf = (kc >> 4) & 1;
        const int nbuf = buf ^ 1;
        const bool more = (kc + KC2) < N_SLOTS_C;
        if (more) {
            q0 = *(const float4*)&mem[(size_t)(kc + KC2 + r2)     * D_MODEL_C + c4b * 4];
            q1 = *(const float4*)&mem[(size_t)(kc + KC2 + r2 + 8) * D_MODEL_C + c4b * 4];
        }
        const float* bb = Stg + buf * (KC2 * 256);
        #pragma unroll
        for (int kk = 0; kk < KC2; kk++) {
            float4 b = *(const float4*)&bb[kk * 256 + cn * 4];
            float bj[4] = {b.x, b.y, b.z, b.w};
            #pragma unroll
            for (int i = 0; i < 8; i++) {
                float a = Ss[(rg * 8 + i) * N_SLOTS_C + kc + kk];  // broadcast
                #pragma unroll
                for (int j = 0; j < 4; j++)
                    acc2[i][j] = fmaf(a, bj[j], acc2[i][j]);
            }
        }
        if (more) {
            float* d = Stg + nbuf * (KC2 * 256);
            *(float4*)&d[(r2)     * 256 + c4b * 4] = q0;
            *(float4*)&d[(r2 + 8) * 256 + c4b * 4] = q1;
        }
        __syncthreads();
    }

    // ---- write R half of output ----
    #pragma unroll
    for (int i = 0; i < 8; i++) {
        int gr = n0 + rg * 8 + i;
        if (gr < N_NODES_C) {
            *(float4*)&outg[(size_t)gr * 512 + 256 + cn * 4] =
                make_float4(acc2[i][0], acc2[i][1], acc2[i][2], acc2[i][3]);
        }
    }

    // ---- write Q copy half (re-read gmem, coalesced) ----
    {
        const float4* q4 = (const float4*)query;
        #pragma unroll
        for (int it = 0; it < 8; it++) {
            int idx = tid + it * THREADS_C;   // 0..4095
            int r = idx >> 6;
            int c4 = idx & 63;
            int gr = n0 + r;
            if (gr < N_NODES_C)
                *(float4*)&outg[(size_t)gr * 512 + c4 * 4] = q4[(size_t)gr * 64 + c4];
        }
    }
}

extern "C" void kernel_launch(void* const* d_in, const int* in_sizes, int n_in,
                              void* d_out, int out_size) {
    const float* query      = (const float*)d_in[0];
    const float* mem_attr   = (const float*)d_in[1];
    const float* mem_struct = (const float*)d_in[2];
    float* out = (float*)d_out;

    cudaFuncSetAttribute(fused_mem_read_v2,
                         cudaFuncAttributeMaxDynamicSharedMemorySize, SMEM_BYTES);

    dim3 grid((N_NODES_C + BLK_M - 1) / BLK_M, 2);
    fused_mem_read_v2<<<grid, THREADS_C, SMEM_BYTES>>>(query, mem_attr, mem_struct, out);
}

// round 4
// speedup vs baseline: 3.8542x; 3.0915x over previous
#include <cuda_runtime.h>
#include <cuda_fp16.h>
#include <math_constants.h>
#include <cstdint>

#define N_NODES 100000
#define D_MODEL 256
#define N_SLOTS 512
#define TILE_M 64
#define THREADS 256
#define N_TILES ((N_NODES + TILE_M - 1) / TILE_M)   // 1563

// smem byte offsets
#define OFF_QH 0          // 32KB  (GEMM1 A hi)   — overlaid by PH
#define OFF_QL 32768      // 32KB  (GEMM1 A lo)   — overlaid by PH tail
#define OFF_PH 0          // 64KB  (GEMM2 A hi)
#define OFF_PL 65536      // 64KB  (GEMM2 A lo)
#define OFF_PMAX 131072   // 2KB   [64][8]
#define OFF_PSUM 133120   // 2KB
#define SMEM_BYTES 135168

// Pre-packed B fragments for mma.sync.m16n8k16.row.col (4 halfs per lane, uint2).
// G1B[mem][split][kt(16)][nt(64)][lane(32)]  : B = M^T  (k=dmodel, n=slot)
// G2B[mem][split][kt(32)][nt(32)][lane(32)]  : B = M    (k=slot,  n=dmodel)
__device__ __align__(16) uint2 G1B[2][2][16][64][32];
__device__ __align__(16) uint2 G2B[2][2][32][32][32];

__device__ __forceinline__ void split2h(float x, float y, uint32_t& hi, uint32_t& lo) {
    __half hx = __float2half_rn(x);
    __half hy = __float2half_rn(y);
    __half lx = __float2half_rn(x - __half2float(hx));
    __half ly = __float2half_rn(y - __half2float(hy));
    __half2 h = __halves2half2(hx, hy);
    __half2 l = __halves2half2(lx, ly);
    hi = *(uint32_t*)&h;
    lo = *(uint32_t*)&l;
}

__device__ __forceinline__ void mma16816(float* c, const uint4& a, const uint2& b) {
    asm volatile(
        "mma.sync.aligned.m16n8k16.row.col.f32.f16.f16.f32 "
        "{%0,%1,%2,%3}, {%4,%5,%6,%7}, {%8,%9}, {%0,%1,%2,%3};"
        : "+f"(c[0]), "+f"(c[1]), "+f"(c[2]), "+f"(c[3])
        : "r"(a.x), "r"(a.y), "r"(a.z), "r"(a.w), "r"(b.x), "r"(b.y));
}

// ---------------- prep: pack memory matrices into B-fragment order ----------------
__global__ void prep_kernel(const float* __restrict__ ma, const float* __restrict__ ms) {
    int idx = blockIdx.x * blockDim.x + threadIdx.x;
    if (idx >= 131072) return;
    bool isG2 = idx >= 65536;
    int r = idx & 65535;
    int lane = r & 31;
    int t = lane & 3, g = lane >> 2;
    if (!isG2) {
        int nt = (r >> 5) & 63;
        int kt = (r >> 11) & 15;
        int mem = (r >> 15) & 1;
        const float* src = mem ? ms : ma;
        int slot = nt * 8 + g;
        int k = kt * 16 + 2 * t;
        float v0 = src[slot * D_MODEL + k];
        float v1 = src[slot * D_MODEL + k + 1];
        float v2 = src[slot * D_MODEL + k + 8];
        float v3 = src[slot * D_MODEL + k + 9];
        uint32_t h01, l01, h23, l23;
        split2h(v0, v1, h01, l01);
        split2h(v2, v3, h23, l23);
        G1B[mem][0][kt][nt][lane] = make_uint2(h01, h23);
        G1B[mem][1][kt][nt][lane] = make_uint2(l01, l23);
    } else {
        int nt = (r >> 5) & 31;
        int kt = (r >> 10) & 31;
        int mem = (r >> 15) & 1;
        const float* src = mem ? ms : ma;
        int col = nt * 8 + g;
        int ks = kt * 16 + 2 * t;
        float v0 = src[(ks)     * D_MODEL + col];
        float v1 = src[(ks + 1) * D_MODEL + col];
        float v2 = src[(ks + 8) * D_MODEL + col];
        float v3 = src[(ks + 9) * D_MODEL + col];
        uint32_t h01, l01, h23, l23;
        split2h(v0, v1, h01, l01);
        split2h(v2, v3, h23, l23);
        G2B[mem][0][kt][nt][lane] = make_uint2(h01, h23);
        G2B[mem][1][kt][nt][lane] = make_uint2(l01, l23);
    }
}

// ---------------- main fused kernel ----------------
__global__ __launch_bounds__(THREADS, 1)
void smgt_hmma(const float* __restrict__ query, float* __restrict__ out) {
    extern __shared__ char smem[];
    const int tid = threadIdx.x;
    const int w = tid >> 5, lane = tid & 31;
    const int t = lane & 3, g = lane >> 2;
    const int memi = blockIdx.y;
    const int n0 = blockIdx.x * TILE_M;
    float* __restrict__ outg = out + (size_t)memi * N_NODES * 512u;

    // ---- load Q tile, split fp16 hi/lo, store in A-fragment-packed layout ----
    #pragma unroll 4
    for (int it = 0; it < 16; it++) {
        int idx = tid + it * THREADS;    // 0..4095 float4s
        int rr = idx >> 6;               // row 0..63
        int c4 = idx & 63;
        int gr = n0 + rr;
        float4 v = make_float4(0.f, 0.f, 0.f, 0.f);
        if (gr < N_NODES) v = ((const float4*)query)[(size_t)gr * 64 + c4];
        int mt = rr >> 4, sr = rr & 15, gg = sr & 7, hr = sr >> 3;
        #pragma unroll
        for (int p = 0; p < 2; p++) {
            int k = c4 * 4 + 2 * p;
            int kt = k >> 4, sk = k & 15;
            int ln = gg * 4 + ((sk & 7) >> 1);
            int off = ((kt * 4 + mt) * 32 + (ln ^ (kt & 7))) * 16 + 4 * hr + 8 * (sk >> 3);
            float x = p ? v.z : v.x;
            float y = p ? v.w : v.y;
            uint32_t hi, lo;
            split2h(x, y, hi, lo);
            *(uint32_t*)(smem + OFF_QH + off) = hi;
            *(uint32_t*)(smem + OFF_QL + off) = lo;
        }
    }
    __syncthreads();

    // ================= GEMM1: S = Q @ M^T (64x512, warp = 64x64) =================
    float acc[4][8][4];
    #pragma unroll
    for (int mt = 0; mt < 4; mt++)
        #pragma unroll
        for (int j = 0; j < 8; j++)
            #pragma unroll
            for (int i = 0; i < 4; i++) acc[mt][j][i] = 0.f;

    #pragma unroll 1
    for (int kt = 0; kt < 16; kt++) {
        uint2 bh[8], bl[8];
        #pragma unroll
        for (int j = 0; j < 8; j++) {
            bh[j] = G1B[memi][0][kt][w * 8 + j][lane];
            bl[j] = G1B[memi][1][kt][w * 8 + j][lane];
        }
        uint4 ah[4], al[4];
        #pragma unroll
        for (int mt = 0; mt < 4; mt++) {
            int chunk = ((kt * 4 + mt) * 32 + (lane ^ (kt & 7))) * 16;
            ah[mt] = *(const uint4*)(smem + OFF_QH + chunk);
            al[mt] = *(const uint4*)(smem + OFF_QL + chunk);
        }
        #pragma unroll
        for (int j = 0; j < 8; j++)
            #pragma unroll
            for (int mt = 0; mt < 4; mt++) {
                mma16816(acc[mt][j], ah[mt], bh[j]);
                mma16816(acc[mt][j], al[mt], bh[j]);
                mma16816(acc[mt][j], ah[mt], bl[j]);
            }
    }

    // ================= softmax over 512 cols (accums hold S) =================
    float* pmax = (float*)(smem + OFF_PMAX);
    float* psum = (float*)(smem + OFF_PSUM);

    #pragma unroll
    for (int mt = 0; mt < 4; mt++)
        #pragma unroll
        for (int i2 = 0; i2 < 2; i2++) {
            float m = -CUDART_INF_F;
            #pragma unroll
            for (int j = 0; j < 8; j++) {
                m = fmaxf(m, acc[mt][j][2 * i2]);
                m = fmaxf(m, acc[mt][j][2 * i2 + 1]);
            }
            m = fmaxf(m, __shfl_xor_sync(0xffffffffu, m, 1));
            m = fmaxf(m, __shfl_xor_sync(0xffffffffu, m, 2));
            if (t == 0) pmax[(mt * 16 + g + 8 * i2) * 8 + w] = m;
        }
    __syncthreads();

    float gmax[4][2];
    #pragma unroll
    for (int mt = 0; mt < 4; mt++)
        #pragma unroll
        for (int i2 = 0; i2 < 2; i2++) {
            int row = mt * 16 + g + 8 * i2;
            float m = pmax[row * 8];
            #pragma unroll
            for (int j = 1; j < 8; j++) m = fmaxf(m, pmax[row * 8 + j]);
            gmax[mt][i2] = m;
        }

    #pragma unroll
    for (int mt = 0; mt < 4; mt++)
        #pragma unroll
        for (int i2 = 0; i2 < 2; i2++) {
            float s = 0.f;
            #pragma unroll
            for (int j = 0; j < 8; j++) {
                float e0 = __expf(acc[mt][j][2 * i2]     - gmax[mt][i2]);
                float e1 = __expf(acc[mt][j][2 * i2 + 1] - gmax[mt][i2]);
                acc[mt][j][2 * i2]     = e0;
                acc[mt][j][2 * i2 + 1] = e1;
                s += e0 + e1;
            }
            s += __shfl_xor_sync(0xffffffffu, s, 1);
            s += __shfl_xor_sync(0xffffffffu, s, 2);
            if (t == 0) psum[(mt * 16 + g + 8 * i2) * 8 + w] = s;
        }
    __syncthreads();

    float inv[4][2];
    #pragma unroll
    for (int mt = 0; mt < 4; mt++)
        #pragma unroll
        for (int i2 = 0; i2 < 2; i2++) {
            int row = mt * 16 + g + 8 * i2;
            float s = psum[row * 8];
            #pragma unroll
            for (int j = 1; j < 8; j++) s += psum[row * 8 + j];
            inv[mt][i2] = 1.f / (s * 16384.f);
        }

    // ---- pack P (scaled by 2^14) into GEMM2 A-fragment layout (overwrites Q) ----
    #pragma unroll
    for (int mt = 0; mt < 4; mt++)
        #pragma unroll
        for (int j = 0; j < 8; j++) {
            int kt2 = w * 4 + (j >> 1);
            int base = ((kt2 * 4 + mt) * 32 + (lane ^ (kt2 & 7))) * 16 + 8 * (j & 1);
            uint32_t hi, lo;
            split2h(acc[mt][j][0] * 16384.f, acc[mt][j][1] * 16384.f, hi, lo);
            *(uint32_t*)(smem + OFF_PH + base) = hi;
            *(uint32_t*)(smem + OFF_PL + base) = lo;
            split2h(acc[mt][j][2] * 16384.f, acc[mt][j][3] * 16384.f, hi, lo);
            *(uint32_t*)(smem + OFF_PH + base + 4) = hi;
            *(uint32_t*)(smem + OFF_PL + base + 4) = lo;
        }
    __syncthreads();

    // ================= GEMM2: R = P @ M (64x256, warp = 64x32) =================
    float a2[4][4][4];
    #pragma unroll
    for (int mt = 0; mt < 4; mt++)
        #pragma unroll
        for (int j = 0; j < 4; j++)
            #pragma unroll
            for (int i = 0; i < 4; i++) a2[mt][j][i] = 0.f;

    #pragma unroll 1
    for (int kt = 0; kt < 32; kt++) {
        uint2 bh[4], bl[4];
        #pragma unroll
        for (int j = 0; j < 4; j++) {
            bh[j] = G2B[memi][0][kt][w * 4 + j][lane];
            bl[j] = G2B[memi][1][kt][w * 4 + j][lane];
        }
        uint4 ph[4], pl[4];
        #pragma unroll
        for (int mt = 0; mt < 4; mt++) {
            int chunk = ((kt * 4 + mt) * 32 + (lane ^ (kt & 7))) * 16;
            ph[mt] = *(const uint4*)(smem + OFF_PH + chunk);
            pl[mt] = *(const uint4*)(smem + OFF_PL + chunk);
        }
        #pragma unroll
        for (int j = 0; j < 4; j++)
            #pragma unroll
            for (int mt = 0; mt < 4; mt++) {
                mma16816(a2[mt][j], ph[mt], bh[j]);
                mma16816(a2[mt][j], pl[mt], bh[j]);
                mma16816(a2[mt][j], ph[mt], bl[j]);
            }
    }

    // ---- epilogue: scale by 1/(sum*2^14), store R half ----
    #pragma unroll
    for (int mt = 0; mt < 4; mt++)
        #pragma unroll
        for (int j = 0; j < 4; j++) {
            int col = w * 32 + j * 8 + 2 * t;
            #pragma unroll
            for (int i2 = 0; i2 < 2; i2++) {
                int gr = n0 + mt * 16 + g + 8 * i2;
                if (gr < N_NODES) {
                    float2 o;
                    o.x = a2[mt][j][2 * i2]     * inv[mt][i2];
                    o.y = a2[mt][j][2 * i2 + 1] * inv[mt][i2];
                    *(float2*)&outg[(size_t)gr * 512 + 256 + col] = o;
                }
            }
        }

    // ---- Q copy half ----
    #pragma unroll 4
    for (int it = 0; it < 16; it++) {
        int idx = tid + it * THREADS;
        int rr = idx >> 6, c4 = idx & 63;
        int gr = n0 + rr;
        if (gr < N_NODES)
            ((float4*)outg)[(size_t)gr * 128 + c4] = ((const float4*)query)[(size_t)gr * 64 + c4];
    }
}

extern "C" void kernel_launch(void* const* d_in, const int* in_sizes, int n_in,
                              void* d_out, int out_size) {
    const float* query      = (const float*)d_in[0];
    const float* mem_attr   = (const float*)d_in[1];
    const float* mem_struct = (const float*)d_in[2];
    float* out = (float*)d_out;

    prep_kernel<<<512, 256>>>(mem_attr, mem_struct);

    cudaFuncSetAttribute(smgt_hmma, cudaFuncAttributeMaxDynamicSharedMemorySize, SMEM_BYTES);
    dim3 grid(N_TILES, 2);
    smgt_hmma<<<grid, THREADS, SMEM_BYTES>>>(query, out);
}

// round 5
// speedup vs baseline: 4.4818x; 1.1628x over previous
#include <cuda_runtime.h>
#include <cuda_fp16.h>
#include <math_constants.h>
#include <cstdint>

#define N_NODES 100000
#define D_MODEL 256
#define N_SLOTS 512
#define TILE_M 64
#define THREADS 256
#define N_TILES ((N_NODES + TILE_M - 1) / TILE_M)   // 1563

// smem byte offsets
#define OFF_QH 0          // 32KB  (GEMM1 A hi)
#define OFF_QL 32768      // 32KB  (GEMM1 A lo)
#define OFF_PH 0          // 64KB  (GEMM2 A hi only — overlays QH+QL)
#define OFF_PMAX 65536    // 2KB [64][8]
#define OFF_PSUM 67584    // 2KB
#define SMEM_BYTES 69632

// Pre-packed B fragments for mma.sync.m16n8k16.row.col (4 halfs per lane, uint2).
// G1B[mem][split][kt(16)][nt(64)][lane(32)]  : B = M^T  (k=dmodel, n=slot)
// G2B[mem][split][kt(32)][nt(32)][lane(32)]  : B = M    (k=slot,  n=dmodel)
__device__ __align__(16) uint2 G1B[2][2][16][64][32];
__device__ __align__(16) uint2 G2B[2][2][32][32][32];

__device__ __forceinline__ void split2h(float x, float y, uint32_t& hi, uint32_t& lo) {
    __half hx = __float2half_rn(x);
    __half hy = __float2half_rn(y);
    __half lx = __float2half_rn(x - __half2float(hx));
    __half ly = __float2half_rn(y - __half2float(hy));
    __half2 h = __halves2half2(hx, hy);
    __half2 l = __halves2half2(lx, ly);
    hi = *(uint32_t*)&h;
    lo = *(uint32_t*)&l;
}

__device__ __forceinline__ uint32_t pack2h(float x, float y) {
    __half2 h = __halves2half2(__float2half_rn(x), __float2half_rn(y));
    return *(uint32_t*)&h;
}

__device__ __forceinline__ void mma16816(float* c, const uint4& a, const uint2& b) {
    asm volatile(
        "mma.sync.aligned.m16n8k16.row.col.f32.f16.f16.f32 "
        "{%0,%1,%2,%3}, {%4,%5,%6,%7}, {%8,%9}, {%0,%1,%2,%3};"
        : "+f"(c[0]), "+f"(c[1]), "+f"(c[2]), "+f"(c[3])
        : "r"(a.x), "r"(a.y), "r"(a.z), "r"(a.w), "r"(b.x), "r"(b.y));
}

// ---------------- prep: pack memory matrices into B-fragment order ----------------
__global__ void prep_kernel(const float* __restrict__ ma, const float* __restrict__ ms) {
    int idx = blockIdx.x * blockDim.x + threadIdx.x;
    if (idx >= 131072) return;
    bool isG2 = idx >= 65536;
    int r = idx & 65535;
    int lane = r & 31;
    int t = lane & 3, g = lane >> 2;
    if (!isG2) {
        int nt = (r >> 5) & 63;
        int kt = (r >> 11) & 15;
        int mem = (r >> 15) & 1;
        const float* src = mem ? ms : ma;
        int slot = nt * 8 + g;
        int k = kt * 16 + 2 * t;
        float v0 = src[slot * D_MODEL + k];
        float v1 = src[slot * D_MODEL + k + 1];
        float v2 = src[slot * D_MODEL + k + 8];
        float v3 = src[slot * D_MODEL + k + 9];
        uint32_t h01, l01, h23, l23;
        split2h(v0, v1, h01, l01);
        split2h(v2, v3, h23, l23);
        G1B[mem][0][kt][nt][lane] = make_uint2(h01, h23);
        G1B[mem][1][kt][nt][lane] = make_uint2(l01, l23);
    } else {
        int nt = (r >> 5) & 31;
        int kt = (r >> 10) & 31;
        int mem = (r >> 15) & 1;
        const float* src = mem ? ms : ma;
        int col = nt * 8 + g;
        int ks = kt * 16 + 2 * t;
        float v0 = src[(ks)     * D_MODEL + col];
        float v1 = src[(ks + 1) * D_MODEL + col];
        float v2 = src[(ks + 8) * D_MODEL + col];
        float v3 = src[(ks + 9) * D_MODEL + col];
        uint32_t h01, l01, h23, l23;
        split2h(v0, v1, h01, l01);
        split2h(v2, v3, h23, l23);
        G2B[mem][0][kt][nt][lane] = make_uint2(h01, h23);
        G2B[mem][1][kt][nt][lane] = make_uint2(l01, l23);
    }
}

// ---------------- main fused kernel ----------------
__global__ __launch_bounds__(THREADS, 1)
void smgt_hmma(const float* __restrict__ query, float* __restrict__ out) {
    extern __shared__ char smem[];
    const int tid = threadIdx.x;
    const int w = tid >> 5, lane = tid & 31;
    const int t = lane & 3, g = lane >> 2;
    const int memi = blockIdx.y;
    const int n0 = blockIdx.x * TILE_M;
    float* __restrict__ outg = out + (size_t)memi * N_NODES * 512u;

    // ---- load Q tile, split fp16 hi/lo, store in A-fragment-packed layout ----
    #pragma unroll 4
    for (int it = 0; it < 16; it++) {
        int idx = tid + it * THREADS;    // 0..4095 float4s
        int rr = idx >> 6;               // row 0..63
        int c4 = idx & 63;
        int gr = n0 + rr;
        float4 v = make_float4(0.f, 0.f, 0.f, 0.f);
        if (gr < N_NODES) v = ((const float4*)query)[(size_t)gr * 64 + c4];
        int mt = rr >> 4, sr = rr & 15, gg = sr & 7, hr = sr >> 3;
        #pragma unroll
        for (int p = 0; p < 2; p++) {
            int k = c4 * 4 + 2 * p;
            int kt = k >> 4, sk = k & 15;
            int ln = gg * 4 + ((sk & 7) >> 1);
            int off = ((kt * 4 + mt) * 32 + (ln ^ (kt & 7))) * 16 + 4 * hr + 8 * (sk >> 3);
            float x = p ? v.z : v.x;
            float y = p ? v.w : v.y;
            uint32_t hi, lo;
            split2h(x, y, hi, lo);
            *(uint32_t*)(smem + OFF_QH + off) = hi;
            *(uint32_t*)(smem + OFF_QL + off) = lo;
        }
    }
    __syncthreads();

    // ================= GEMM1: S = Q @ M^T (64x512, warp = 64x64) =================
    float acc[4][8][4];
    #pragma unroll
    for (int mt = 0; mt < 4; mt++)
        #pragma unroll
        for (int j = 0; j < 8; j++)
            #pragma unroll
            for (int i = 0; i < 4; i++) acc[mt][j][i] = 0.f;

    {
        const uint2* __restrict__ g1h = &G1B[memi][0][0][w * 8][0];
        const uint2* __restrict__ g1l = &G1B[memi][1][0][w * 8][0];
        // element (kt, h, j): kt*2048 + (h*4+j)*32 + lane   (uint2 units)
        uint2 bh[2][4], bl[2][4];
        #pragma unroll
        for (int j = 0; j < 4; j++) {
            bh[0][j] = g1h[j * 32 + lane];
            bl[0][j] = g1l[j * 32 + lane];
        }

        #pragma unroll 1
        for (int kt = 0; kt < 16; kt++) {
            uint4 ah[4], al[4];
            #pragma unroll
            for (int mt = 0; mt < 4; mt++) {
                int chunk = ((kt * 4 + mt) * 32 + (lane ^ (kt & 7))) * 16;
                ah[mt] = *(const uint4*)(smem + OFF_QH + chunk);
                al[mt] = *(const uint4*)(smem + OFF_QL + chunk);
            }

            // ---- half h=0: compute buf0, prefetch (kt, h=1) -> buf1 ----
            {
                int base = kt * 2048 + 128 + lane;
                #pragma unroll
                for (int j = 0; j < 4; j++) {
                    bh[1][j] = g1h[base + j * 32];
                    bl[1][j] = g1l[base + j * 32];
                }
                #pragma unroll
                for (int j = 0; j < 4; j++)
                    #pragma unroll
                    for (int mt = 0; mt < 4; mt++) {
                        mma16816(acc[mt][j], ah[mt], bh[0][j]);
                        mma16816(acc[mt][j], al[mt], bh[0][j]);
                        mma16816(acc[mt][j], ah[mt], bl[0][j]);
                    }
            }
            // ---- half h=1: compute buf1, prefetch (kt+1, h=0) -> buf0 ----
            {
                if (kt + 1 < 16) {
                    int base = (kt + 1) * 2048 + lane;
                    #pragma unroll
                    for (int j = 0; j < 4; j++) {
                        bh[0][j] = g1h[base + j * 32];
                        bl[0][j] = g1l[base + j * 32];
                    }
                }
                #pragma unroll
                for (int j = 0; j < 4; j++)
                    #pragma unroll
                    for (int mt = 0; mt < 4; mt++) {
                        mma16816(acc[mt][4 + j], ah[mt], bh[1][j]);
                        mma16816(acc[mt][4 + j], al[mt], bh[1][j]);
                        mma16816(acc[mt][4 + j], ah[mt], bl[1][j]);
                    }
            }
        }
    }

    // ================= softmax over 512 cols (accums hold S) =================
    float* pmax = (float*)(smem + OFF_PMAX);
    float* psum = (float*)(smem + OFF_PSUM);

    #pragma unroll
    for (int mt = 0; mt < 4; mt++)
        #pragma unroll
        for (int i2 = 0; i2 < 2; i2++) {
            float m = -CUDART_INF_F;
            #pragma unroll
            for (int j = 0; j < 8; j++) {
                m = fmaxf(m, acc[mt][j][2 * i2]);
                m = fmaxf(m, acc[mt][j][2 * i2 + 1]);
            }
            m = fmaxf(m, __shfl_xor_sync(0xffffffffu, m, 1));
            m = fmaxf(m, __shfl_xor_sync(0xffffffffu, m, 2));
            if (t == 0) pmax[(mt * 16 + g + 8 * i2) * 8 + w] = m;
        }
    __syncthreads();

    float gmax[4][2];
    #pragma unroll
    for (int mt = 0; mt < 4; mt++)
        #pragma unroll
        for (int i2 = 0; i2 < 2; i2++) {
            int row = mt * 16 + g + 8 * i2;
            float m = pmax[row * 8];
            #pragma unroll
            for (int j = 1; j < 8; j++) m = fmaxf(m, pmax[row * 8 + j]);
            gmax[mt][i2] = m;
        }

    #pragma unroll
    for (int mt = 0; mt < 4; mt++)
        #pragma unroll
        for (int i2 = 0; i2 < 2; i2++) {
            float s = 0.f;
            #pragma unroll
            for (int j = 0; j < 8; j++) {
                float e0 = __expf(acc[mt][j][2 * i2]     - gmax[mt][i2]);
                float e1 = __expf(acc[mt][j][2 * i2 + 1] - gmax[mt][i2]);
                acc[mt][j][2 * i2]     = e0;
                acc[mt][j][2 * i2 + 1] = e1;
                s += e0 + e1;
            }
            s += __shfl_xor_sync(0xffffffffu, s, 1);
            s += __shfl_xor_sync(0xffffffffu, s, 2);
            if (t == 0) psum[(mt * 16 + g + 8 * i2) * 8 + w] = s;
        }
    __syncthreads();

    float inv[4][2];
    #pragma unroll
    for (int mt = 0; mt < 4; mt++)
        #pragma unroll
        for (int i2 = 0; i2 < 2; i2++) {
            int row = mt * 16 + g + 8 * i2;
            float s = psum[row * 8];
            #pragma unroll
            for (int j = 1; j < 8; j++) s += psum[row * 8 + j];
            inv[mt][i2] = 1.f / (s * 16384.f);
        }

    // ---- pack P hi only (scaled by 2^14) into GEMM2 A layout (overwrites Q) ----
    #pragma unroll
    for (int mt = 0; mt < 4; mt++)
        #pragma unroll
        for (int j = 0; j < 8; j++) {
            int kt2 = w * 4 + (j >> 1);
            int base = ((kt2 * 4 + mt) * 32 + (lane ^ (kt2 & 7))) * 16 + 8 * (j & 1);
            *(uint32_t*)(smem + OFF_PH + base)     = pack2h(acc[mt][j][0] * 16384.f,
                                                            acc[mt][j][1] * 16384.f);
            *(uint32_t*)(smem + OFF_PH + base + 4) = pack2h(acc[mt][j][2] * 16384.f,
                                                            acc[mt][j][3] * 16384.f);
        }
    __syncthreads();

    // ================= GEMM2: R = P @ M (64x256, warp = 64x32, 2-term) =================
    float a2[4][4][4];
    #pragma unroll
    for (int mt = 0; mt < 4; mt++)
        #pragma unroll
        for (int j = 0; j < 4; j++)
            #pragma unroll
            for (int i = 0; i < 4; i++) a2[mt][j][i] = 0.f;

    {
        const uint2* __restrict__ g2h = &G2B[memi][0][0][w * 4][0];
        const uint2* __restrict__ g2l = &G2B[memi][1][0][w * 4][0];
        // element (kt, j): kt*1024 + j*32 + lane
        uint2 ch[2][4], cl[2][4];
        #pragma unroll
        for (int j = 0; j < 4; j++) {
            ch[0][j] = g2h[j * 32 + lane];
            cl[0][j] = g2l[j * 32 + lane];
        }

        #pragma unroll 1
        for (int kp = 0; kp < 16; kp++) {
            // ---- kt = 2*kp (buf0), prefetch kt+1 -> buf1 ----
            {
                int kt = 2 * kp;
                uint4 ph[4];
                #pragma unroll
                for (int mt = 0; mt < 4; mt++) {
                    int chunk = ((kt * 4 + mt) * 32 + (lane ^ (kt & 7))) * 16;
                    ph[mt] = *(const uint4*)(smem + OFF_PH + chunk);
                }
                int base = (kt + 1) * 1024 + lane;
                #pragma unroll
                for (int j = 0; j < 4; j++) {
                    ch[1][j] = g2h[base + j * 32];
                    cl[1][j] = g2l[base + j * 32];
                }
                #pragma unroll
                for (int j = 0; j < 4; j++)
                    #pragma unroll
                    for (int mt = 0; mt < 4; mt++) {
                        mma16816(a2[mt][j], ph[mt], ch[0][j]);
                        mma16816(a2[mt][j], ph[mt], cl[0][j]);
                    }
            }
            // ---- kt = 2*kp+1 (buf1), prefetch kt+1 -> buf0 ----
            {
                int kt = 2 * kp + 1;
                uint4 ph[4];
                #pragma unroll
                for (int mt = 0; mt < 4; mt++) {
                    int chunk = ((kt * 4 + mt) * 32 + (lane ^ (kt & 7))) * 16;
                    ph[mt] = *(const uint4*)(smem + OFF_PH + chunk);
                }
                if (kt + 1 < 32) {
                    int base = (kt + 1) * 1024 + lane;
                    #pragma unroll
                    for (int j = 0; j < 4; j++) {
                        ch[0][j] = g2h[base + j * 32];
                        cl[0][j] = g2l[base + j * 32];
                    }
                }
                #pragma unroll
                for (int j = 0; j < 4; j++)
                    #pragma unroll
                    for (int mt = 0; mt < 4; mt++) {
                        mma16816(a2[mt][j], ph[mt], ch[1][j]);
                        mma16816(a2[mt][j], ph[mt], cl[1][j]);
                    }
            }
        }
    }

    // ---- epilogue: scale by 1/(sum*2^14), store R half ----
    #pragma unroll
    for (int mt = 0; mt < 4; mt++)
        #pragma unroll
        for (int j = 0; j < 4; j++) {
            int col = w * 32 + j * 8 + 2 * t;
            #pragma unroll
            for (int i2 = 0; i2 < 2; i2++) {
                int gr = n0 + mt * 16 + g + 8 * i2;
                if (gr < N_NODES) {
                    float2 o;
                    o.x = a2[mt][j][2 * i2]     * inv[mt][i2];
                    o.y = a2[mt][j][2 * i2 + 1] * inv[mt][i2];
                    *(float2*)&outg[(size_t)gr * 512 + 256 + col] = o;
                }
            }
        }

    // ---- Q copy half ----
    #pragma unroll 4
    for (int it = 0; it < 16; it++) {
        int idx = tid + it * THREADS;
        int rr = idx >> 6, c4 = idx & 63;
        int gr = n0 + rr;
        if (gr < N_NODES)
            ((float4*)outg)[(size_t)gr * 128 + c4] = ((const float4*)query)[(size_t)gr * 64 + c4];
    }
}

extern "C" void kernel_launch(void* const* d_in, const int* in_sizes, int n_in,
                              void* d_out, int out_size) {
    const float* query      = (const float*)d_in[0];
    const float* mem_attr   = (const float*)d_in[1];
    const float* mem_struct = (const float*)d_in[2];
    float* out = (float*)d_out;

    prep_kernel<<<512, 256>>>(mem_attr, mem_struct);

    cudaFuncSetAttribute(smgt_hmma, cudaFuncAttributeMaxDynamicSharedMemorySize, SMEM_BYTES);
    dim3 grid(N_TILES, 2);
    smgt_hmma<<<grid, THREADS, SMEM_BYTES>>>(query, out);
}